// round 17
// baseline (speedup 1.0000x reference)
#include <cuda_runtime.h>
#include <cuda_bf16.h>
#include <cstdint>

#define BB 32
#define TT 512
#define II 128
#define HH 1024
#define GG 4096
#define OO 128

#define NTH 512
#define NBLK 66

#define RSB 272             // padded row stride (bytes) for 128-bf16 rows
#define STAGE_BYTES 52224   // Ahi 17408 | Alo 17408 | Bhi 8704 | Blo 8704
#define OFF_ALO 17408
#define OFF_BHI 34816
#define OFF_BLO 43520
#define RING 3
#define DEX_OFF 156672      // bytes; Dex4: 4 x (64x33) f32 = 33792B
#define SMEM_BYTES 190464

// ---------------- device scratch ----------------
__device__ __nv_bfloat16 Wih0hi[GG * II], Wih0lo[GG * II];   // [n][k], n = j*4+g
__device__ __nv_bfloat16 Whh0hi[GG * HH], Whh0lo[GG * HH];
__device__ __nv_bfloat16 Wih1hi[GG * HH], Wih1lo[GG * HH];
__device__ __nv_bfloat16 Whh1hi[GG * HH], Whh1lo[GG * HH];
__device__ __nv_bfloat16 Wohi[OO * HH],  Wolo[OO * HH];      // [o][k]
__device__ float gbp0[GG], gbp1[GG];
__device__ __nv_bfloat16 xhi[TT * BB * II], xlo[TT * BB * II];  // [t][b][k]
__device__ __nv_bfloat16 h0hi[2][BB * HH], h0lo[2][BB * HH];    // [b][j]
__device__ __nv_bfloat16 h2hi[2][BB * HH], h2lo[2][BB * HH];
__device__ unsigned g_cnt, g_flag;

// ---------------- prep ----------------
__device__ __forceinline__ void split2(float v, __nv_bfloat16* hi, __nv_bfloat16* lo) {
    __nv_bfloat16 h = __float2bfloat16(v);
    *hi = h;
    *lo = __float2bfloat16(v - __bfloat162float(h));
}

__global__ void prep_kernel(const float* __restrict__ xin,
                            const float* __restrict__ Wih0, const float* __restrict__ Whh0,
                            const float* __restrict__ b0v, const float* __restrict__ Wih1,
                            const float* __restrict__ Whh1, const float* __restrict__ b1v,
                            const float* __restrict__ Wout) {
    int idx0 = blockIdx.x * blockDim.x + threadIdx.x;
    int stride = gridDim.x * blockDim.x;
    if (idx0 == 0) { g_cnt = 0u; g_flag = 0u; }

    const __nv_bfloat16 z = __float2bfloat16(0.f);
    for (int i = idx0; i < 2 * BB * HH; i += stride) {
        ((__nv_bfloat16*)h0hi)[i] = z;
        ((__nv_bfloat16*)h0lo)[i] = z;
        ((__nv_bfloat16*)h2hi)[i] = z;
        ((__nv_bfloat16*)h2lo)[i] = z;
    }

    const int SW0 = GG * II;
    const int SW1 = GG * HH;
    const int SWO = OO * HH;
    const int SXX = TT * BB * II;
    const int total = SW0 + 3 * SW1 + SWO + SXX + 2 * GG;
    for (int idx = idx0; idx < total; idx += stride) {
        int r = idx;
        if (r < SW0) {
            int n = r >> 7, k = r & (II - 1);
            int j = n >> 2, g = n & 3;
            split2(Wih0[(g * HH + j) * II + k], &Wih0hi[r], &Wih0lo[r]);
        } else if ((r -= SW0) < SW1) {
            int n = r >> 10, k = r & (HH - 1);
            int j = n >> 2, g = n & 3;
            split2(Whh0[(size_t)(g * HH + j) * HH + k], &Whh0hi[r], &Whh0lo[r]);
        } else if ((r -= SW1) < SW1) {
            int n = r >> 10, k = r & (HH - 1);
            int j = n >> 2, g = n & 3;
            split2(Wih1[(size_t)(g * HH + j) * HH + k], &Wih1hi[r], &Wih1lo[r]);
        } else if ((r -= SW1) < SW1) {
            int n = r >> 10, k = r & (HH - 1);
            int j = n >> 2, g = n & 3;
            split2(Whh1[(size_t)(g * HH + j) * HH + k], &Whh1hi[r], &Whh1lo[r]);
        } else if ((r -= SW1) < SWO) {
            split2(Wout[r], &Wohi[r], &Wolo[r]);   // [o][k] natural
        } else if ((r -= SWO) < SXX) {
            int k = r & (II - 1), b = (r >> 7) & (BB - 1), t = r >> 12;
            split2(xin[((size_t)b * TT + t) * II + k], &xhi[r], &xlo[r]);
        } else if ((r -= SXX) < GG) {
            gbp0[r] = b0v[(r & 3) * HH + (r >> 2)];
        } else {
            r -= GG;
            gbp1[r] = b1v[(r & 3) * HH + (r >> 2)];
        }
    }
}

// ---------------- helpers ----------------
__device__ __forceinline__ void cpa16(uint32_t dst, const void* src) {
    asm volatile("cp.async.cg.shared.global [%0], [%1], 16;" :: "r"(dst), "l"(src));
}
#define CP_COMMIT() asm volatile("cp.async.commit_group;")

#define LDM4(r, a) \
    asm volatile("ldmatrix.sync.aligned.m8n8.x4.shared.b16 {%0,%1,%2,%3}, [%4];" \
        : "=r"((r)[0]), "=r"((r)[1]), "=r"((r)[2]), "=r"((r)[3]) : "r"(a))

#define MMA16(c, A, b0_, b1_) \
    asm volatile("mma.sync.aligned.m16n8k16.row.col.f32.bf16.bf16.f32 " \
        "{%0,%1,%2,%3},{%4,%5,%6,%7},{%8,%9},{%0,%1,%2,%3};" \
        : "+f"((c)[0]), "+f"((c)[1]), "+f"((c)[2]), "+f"((c)[3]) \
        : "r"((A)[0]), "r"((A)[1]), "r"((A)[2]), "r"((A)[3]), "r"(b0_), "r"(b1_))

__device__ __forceinline__ float sigf(float x) { return 1.0f / (1.0f + __expf(-x)); }
__device__ __forceinline__ float tanhfast(float x) {
    return 1.0f - __fdividef(2.0f, __expf(2.0f * x) + 1.0f);
}

// ---------------- grid barrier (sense/epoch) ----------------
__device__ __forceinline__ void grid_bar(int p) {
    __threadfence();
    __syncthreads();
    if (threadIdx.x == 0) {
        unsigned tgt = (unsigned)(p + 1);
        unsigned old = atomicAdd(&g_cnt, 1u);
        if (old == tgt * NBLK - 1u) {
            asm volatile("st.global.release.gpu.u32 [%0], %1;" :: "l"(&g_flag), "r"(tgt) : "memory");
        } else {
            unsigned v;
            do {
                asm volatile("ld.global.acquire.gpu.u32 %0, [%1];" : "=r"(v) : "l"(&g_flag) : "memory");
                if (v >= tgt) break;
                __nanosleep(64);
            } while (true);
        }
    }
    __syncthreads();
}

// ---------------- stage producer (64-gate A tile + 32-batch B tile, k128) ----------------
// ROLE 0: L0 K=1152 (stage0 = x/Wih0, 1..8 = h0/Whh0); ROLE 1: L1 K=2048; ROLE 2: head K=1024
template <int ROLE>
__device__ __forceinline__ void produce(int s, unsigned slot, int t, int tile, int prev,
                                        uint32_t smem_b) {
    const int tid = threadIdx.x;
    const __nv_bfloat16 *Ah, *Al, *Bh, *Bl;
    int sA, sB;
    if (ROLE == 0) {
        if (s == 0) {
            size_t ao = (size_t)tile * 64 * II;
            Ah = Wih0hi + ao; Al = Wih0lo + ao; sA = II;
            size_t bo = (size_t)t * BB * II;
            Bh = xhi + bo; Bl = xlo + bo; sB = II;
        } else {
            int kb = (s - 1) * 128;
            size_t ao = (size_t)tile * 64 * HH + kb;
            Ah = Whh0hi + ao; Al = Whh0lo + ao; sA = HH;
            Bh = h0hi[prev] + kb; Bl = h0lo[prev] + kb; sB = HH;
        }
    } else if (ROLE == 1) {
        if (s < 8) {
            int kb = s * 128;
            size_t ao = (size_t)tile * 64 * HH + kb;
            Ah = Wih1hi + ao; Al = Wih1lo + ao; sA = HH;
            Bh = h0hi[prev] + kb; Bl = h0lo[prev] + kb; sB = HH;
        } else {
            int kb = (s - 8) * 128;
            size_t ao = (size_t)tile * 64 * HH + kb;
            Ah = Whh1hi + ao; Al = Whh1lo + ao; sA = HH;
            Bh = h2hi[prev] + kb; Bl = h2lo[prev] + kb; sB = HH;
        }
    } else {
        int kb = s * 128;
        size_t ao = (size_t)tile * 64 * HH + kb;
        Ah = Wohi + ao; Al = Wolo + ao; sA = HH;
        Bh = h2hi[prev] + kb; Bl = h2lo[prev] + kb; sB = HH;
    }
    const uint32_t base = smem_b + slot * STAGE_BYTES;
    // A hi/lo: 64 rows x 16 chunks (full 256B row) = 1024 chunks each; 2/thread/matrix
#pragma unroll
    for (int u = 0; u < 2; ++u) {
        int id = tid + u * NTH;
        int row = id >> 4, part = id & 15;
        uint32_t doff = (unsigned)(row * RSB + part * 16);
        cpa16(base + doff,           Ah + (size_t)row * sA + part * 8);
        cpa16(base + OFF_ALO + doff, Al + (size_t)row * sA + part * 8);
    }
    // B hi/lo: 32 rows x 16 chunks = 512 chunks each; 1/thread/matrix
    {
        int row = tid >> 4, part = tid & 15;
        uint32_t doff = (unsigned)(row * RSB + part * 16);
        cpa16(base + OFF_BHI + doff, Bh + (size_t)row * sB + part * 8);
        cpa16(base + OFF_BLO + doff, Bl + (size_t)row * sB + part * 8);
    }
}

// ---------------- one phase: D[64 gates x 32 batch] = W . inp^T, then epilogue ----
// 16 warps = 4 m16-tiles x 4 k32-slices (jj loop over 2 k16 halves)
template <int ROLE, int NS>
__device__ __forceinline__ void phase(int p, int t, int tile, uint32_t smem_b, float* smemf,
                                      const float* __restrict__ b_out,
                                      float* __restrict__ out,
                                      float* cstp, unsigned& rs) {
    const int tid = threadIdx.x;
    const int lane = tid & 31, wid = tid >> 5;
    const int mt = wid & 3;     // m16 tile (rows mt*16..)
    const int kq = wid >> 2;    // k32 slice (0..3)
    const int par = p & 1, prev = par ^ 1;

    float C[4][4];
#pragma unroll
    for (int n = 0; n < 4; ++n)
#pragma unroll
        for (int q = 0; q < 4; ++q) C[n][q] = 0.f;

    produce<ROLE>(0, rs % 3u, t, tile, prev, smem_b); CP_COMMIT();
    produce<ROLE>(1, (rs + 1) % 3u, t, tile, prev, smem_b); CP_COMMIT();

    for (int s = 0; s < NS; ++s) {
        if (s + 1 < NS) asm volatile("cp.async.wait_group 1;");
        else            asm volatile("cp.async.wait_group 0;");
        __syncthreads();
        if (s + 2 < NS) {
            produce<ROLE>(s + 2, (rs + s + 2) % 3u, t, tile, prev, smem_b);
            CP_COMMIT();
        }

        const uint32_t slot = smem_b + ((rs + s) % 3u) * STAGE_BYTES;
        // A: rows mt*16 + (lane&15); k-half (lane>>4)*16B; k32 window kq*64B
        uint32_t aH = slot + (unsigned)((mt * 16 + (lane & 15)) * RSB + (lane >> 4) * 16 + kq * 64);
        uint32_t aL = aH + OFF_ALO;
        // B (x4 = 2 n8-tiles x k16): rows (lane&7)+((lane>>4)<<3); k-half ((lane>>3)&1)*16B
        const uint32_t brow = (unsigned)(((lane & 7) + ((lane >> 4) << 3)) * RSB +
                                         ((lane >> 3) & 1) * 16 + kq * 64);
        uint32_t b0H = slot + OFF_BHI + brow;
        uint32_t b1H = b0H + 16 * RSB;
        uint32_t b0L = slot + OFF_BLO + brow;
        uint32_t b1L = b0L + 16 * RSB;

#pragma unroll
        for (int jj = 0; jj < 2; ++jj) {
            uint32_t ah[4], al[4], bh0[4], bh1[4], bl0[4], bl1[4];
            LDM4(ah, aH); LDM4(al, aL);
            LDM4(bh0, b0H); LDM4(bh1, b1H);
            LDM4(bl0, b0L); LDM4(bl1, b1L);
            // term Ah*Bh
            MMA16(C[0], ah, bh0[0], bh0[1]); MMA16(C[1], ah, bh0[2], bh0[3]);
            MMA16(C[2], ah, bh1[0], bh1[1]); MMA16(C[3], ah, bh1[2], bh1[3]);
            // term Ah*Bl
            MMA16(C[0], ah, bl0[0], bl0[1]); MMA16(C[1], ah, bl0[2], bl0[3]);
            MMA16(C[2], ah, bl1[0], bl1[1]); MMA16(C[3], ah, bl1[2], bl1[3]);
            // term Al*Bh
            MMA16(C[0], al, bh0[0], bh0[1]); MMA16(C[1], al, bh0[2], bh0[3]);
            MMA16(C[2], al, bh1[0], bh1[1]); MMA16(C[3], al, bh1[2], bh1[3]);
            aH += 32; aL += 32; b0H += 32; b1H += 32; b0L += 32; b1L += 32;
        }
    }
    rs += NS;

    // ---- dump C to Dex4[kq] (64 rows x 33-float stride) ----
    float* Dex = smemf + DEX_OFF / 4 + kq * (64 * 33);
    const int r0 = mt * 16 + (lane >> 2);
    const int c0 = (lane & 3) * 2;
#pragma unroll
    for (int n = 0; n < 4; ++n) {
        Dex[r0 * 33 + n * 8 + c0]           = C[n][0];
        Dex[r0 * 33 + n * 8 + c0 + 1]       = C[n][1];
        Dex[(r0 + 8) * 33 + n * 8 + c0]     = C[n][2];
        Dex[(r0 + 8) * 33 + n * 8 + c0 + 1] = C[n][3];
    }
    __syncthreads();

    float* D0 = smemf + DEX_OFF / 4;
    if (ROLE < 2) {
        const int jl = tid >> 5;     // hidden unit (local 0..15)
        const int b = lane;          // batch
        float sg[4];
#pragma unroll
        for (int g = 0; g < 4; ++g) {
            int ro = (4 * jl + g) * 33 + b;
            sg[g] = D0[ro] + D0[ro + 2112] + D0[ro + 4224] + D0[ro + 6336];
        }
        const float* gbv = (ROLE == 0) ? gbp0 : gbp1;
        const int nb = tile * 64 + 4 * jl;
        float ig = sigf(sg[0] + gbv[nb]);
        float fg = sigf(sg[1] + gbv[nb + 1]);
        float gt = tanhfast(sg[2] + gbv[nb + 2]);
        float og = sigf(sg[3] + gbv[nb + 3]);
        float cn = fg * (*cstp) + ig * gt;
        *cstp = cn;
        float h = og * tanhfast(cn);
        __nv_bfloat16 hh = __float2bfloat16(h);
        __nv_bfloat16 hl = __float2bfloat16(h - __bfloat162float(hh));
        const int jg = tile * 16 + jl;
        __nv_bfloat16* dh = (ROLE == 0) ? h0hi[par] : h2hi[par];
        __nv_bfloat16* dl = (ROLE == 0) ? h0lo[par] : h2lo[par];
        dh[(size_t)b * HH + jg] = hh;
        dl[(size_t)b * HH + jg] = hl;
    } else {
        const int b = lane;
#pragma unroll
        for (int q4 = 0; q4 < 4; ++q4) {
            int ol = (tid >> 5) + q4 * 16;
            int ro = ol * 33 + b;
            float v = D0[ro] + D0[ro + 2112] + D0[ro + 4224] + D0[ro + 6336];
            int og = tile * 64 + ol;
            out[((size_t)b * TT + t) * OO + og] = v + b_out[og];
        }
    }
    __syncthreads();
}

// ---------------- persistent kernel ----------------
extern __shared__ float smemf[];

__global__ void __launch_bounds__(NTH, 1)
lstm_kernel(const float* __restrict__ b_out, float* __restrict__ out) {
    const int bid = blockIdx.x;
    const uint32_t smem_b = (uint32_t)__cvta_generic_to_shared(smemf);
    float cst[2] = {0.f, 0.f};
    unsigned rs = 0;

    if (bid < 64) {
        // combined: L0 tile bid at t=p, then L1 tile bid at t=p-1 (64 gates each)
        for (int p = 0; p < TT + 2; ++p) {
            if (p < TT)
                phase<0, 9>(p, p, bid, smem_b, smemf, b_out, out, &cst[0], rs);
            if (p >= 1 && p <= TT)
                phase<1, 16>(p, p - 1, bid, smem_b, smemf, b_out, out, &cst[1], rs);
            grid_bar(p);
        }
    } else {
        const int tile = bid - 64;   // head tiles 0..1 (64 out-rows each)
        for (int p = 0; p < TT + 2; ++p) {
            if (p >= 2)
                phase<2, 8>(p, p - 2, tile, smem_b, smemf, b_out, out, &cst[0], rs);
            grid_bar(p);
        }
    }
}

// ---------------- launch ----------------
extern "C" void kernel_launch(void* const* d_in, const int* in_sizes, int n_in,
                              void* d_out, int out_size) {
    const float* x     = (const float*)d_in[0];
    const float* Wih0  = (const float*)d_in[1];
    const float* Whh0  = (const float*)d_in[2];
    const float* b0v   = (const float*)d_in[3];
    const float* Wih1  = (const float*)d_in[4];
    const float* Whh1  = (const float*)d_in[5];
    const float* b1v   = (const float*)d_in[6];
    const float* Wout  = (const float*)d_in[7];
    const float* boutv = (const float*)d_in[8];
    float* out = (float*)d_out;

    // Must NOT run during graph capture (capture-poisoning API call):
    // first harness call is uncaptured -> set once, replays skip.
    static bool attr_set = false;
    if (!attr_set) {
        cudaFuncSetAttribute(lstm_kernel, cudaFuncAttributeMaxDynamicSharedMemorySize, SMEM_BYTES);
        attr_set = true;
    }

    prep_kernel<<<512, 256>>>(x, Wih0, Whh0, b0v, Wih1, Whh1, b1v, Wout);
    lstm_kernel<<<NBLK, NTH, SMEM_BYTES>>>(boutv, out);
}